// round 13
// baseline (speedup 1.0000x reference)
#include <cuda_runtime.h>

// Problem constants
#define Bdim 4
#define Cdim 16
#define Ldim 512
#define Hdim 1024

// Scratch: [2][B][L][C] floats, channel contiguous. 256 KB (lives in L2).
__device__ float g_scratch[2 * Bdim * Ldim * Cdim];

// Side stream + events, created once at module load (host resources only;
// created outside the harness's per-call memory checkpoints, never during
// graph capture).
static cudaStream_t g_s2;
static cudaEvent_t  g_evD[Bdim];
static cudaEvent_t  g_evA;
static struct StreamInit {
    StreamInit() {
        cudaStreamCreateWithFlags(&g_s2, cudaStreamNonBlocking);
        for (int i = 0; i < Bdim; i++)
            cudaEventCreateWithFlags(&g_evD[i], cudaEventDisableTiming);
        cudaEventCreateWithFlags(&g_evA, cudaEventDisableTiming);
    }
} g_stream_init;

// ---------------------------------------------------------------------------
// Kernel A, per-batch: 8192 warps x 2 rows covers one batch of both tensors.
// warp w in [0, 8192): t = w>>12, c = (w>>8)&15, l = (w&255)*2.
// Round-2 inner loop (best measured); __ldcs streaming.
// ---------------------------------------------------------------------------
__global__ void __launch_bounds__(256) dot_kernel(
    const float* __restrict__ start,
    const float* __restrict__ end,
    const float* __restrict__ v,
    int b)
{
    const unsigned warp = (blockIdx.x * blockDim.x + threadIdx.x) >> 5;
    const unsigned lane = threadIdx.x & 31;

    const unsigned t = warp >> 12;              // tensor 0/1
    const unsigned c = (warp >> 8) & 15u;       // channel
    const unsigned l = (warp & 255u) * 2u;      // first of 2 rows

    const float* base = t ? end : start;
    const float4* row0 = (const float4*)
        (base + (size_t)((b * Cdim + c) * Ldim + l) * Hdim);
    const float4* v4 = (const float4*)(v + t * Hdim);

    float sum0 = 0.f, sum1 = 0.f;
#pragma unroll
    for (int k = 0; k < Hdim / 4 / 32; k++) {   // 8 iterations
        const unsigned o = lane + 32 * k;
        float4 a0 = __ldcs(&row0[o]);
        float4 a1 = __ldcs(&row0[o + Hdim / 4]);
        float4 w  = v4[o];
        sum0 += a0.x * w.x + a0.y * w.y + a0.z * w.z + a0.w * w.w;
        sum1 += a1.x * w.x + a1.y * w.y + a1.z * w.z + a1.w * w.w;
    }
#pragma unroll
    for (int o = 16; o; o >>= 1) {
        sum0 += __shfl_xor_sync(0xFFFFFFFFu, sum0, o);
        sum1 += __shfl_xor_sync(0xFFFFFFFFu, sum1, o);
    }

    if (lane == 0) {
        float* dst = &g_scratch[((t * Bdim + b) * Ldim + l) * Cdim + c];
        dst[0]    = sum0;
        dst[Cdim] = sum1;
    }
}

// ---------------------------------------------------------------------------
// Kernel B, per-batch (round-2 tile body, best measured): smem-tiled add.
// Block covers (8 i's, 64 j's, all 16 c) of batch b = 32 KB output.
// ---------------------------------------------------------------------------
__global__ void __launch_bounds__(256) add_kernel(float4* __restrict__ out, int b)
{
    __shared__ float4 e_sm[64 * 4];   // [j][q]
    __shared__ float4 s_sm[8 * 4];    // [i][q]

    const unsigned bx = blockIdx.x;
    const unsigned jt = bx & 7;           // j tile (64 j each)
    const unsigned it = bx >> 3;          // i tile (8 i each), 0..63

    const unsigned t = threadIdx.x;
    const float4* sc4 = (const float4*)g_scratch;   // [2][B][L][4] float4

    e_sm[t] = sc4[((Bdim + b) * Ldim + jt * 64) * (Cdim / 4) + t];
    if (t < 32)
        s_sm[t] = sc4[(b * Ldim + it * 8) * (Cdim / 4) + t];
    __syncthreads();

    const unsigned q = t & 3;
    const unsigned j = t >> 2;
    const float4 e = e_sm[j * 4 + q];

    float4* dst = &out[(((b * Ldim + it * 8) * Ldim) + jt * 64 + j) * 4 + q];

#pragma unroll
    for (int i = 0; i < 8; i++) {
        float4 s = s_sm[i * 4 + q];
        dst[(size_t)i * Ldim * 4] =
            make_float4(s.x + e.x, s.y + e.y, s.z + e.z, s.w + e.w);
    }
}

extern "C" void kernel_launch(void* const* d_in, const int* in_sizes, int n_in,
                              void* d_out, int out_size)
{
    const float* start = (const float*)d_in[0];
    const float* end   = (const float*)d_in[1];
    const float* v     = (const float*)d_in[2];
    float4* out = (float4*)d_out;

    // Pipeline: dot batches serialize on stream 0; each add batch runs on
    // the side stream as soon as its producer batch's event fires, so
    // add_b0..b2 overlap dot_b1..b3. Event fork/join is graph-capturable.
    for (int b = 0; b < Bdim; b++) {
        dot_kernel<<<1024, 256, 0, 0>>>(start, end, v, b);
        cudaEventRecord(g_evD[b], 0);
    }
    for (int b = 0; b < Bdim; b++) {
        cudaStreamWaitEvent(g_s2, g_evD[b], 0);
        add_kernel<<<512, 256, 0, g_s2>>>(out, b);
    }
    cudaEventRecord(g_evA, g_s2);
    cudaStreamWaitEvent(0, g_evA, 0);     // join back to origin stream
}

// round 14
// speedup vs baseline: 1.2456x; 1.2456x over previous
#include <cuda_runtime.h>

// Problem constants
#define Bdim 4
#define Cdim 16
#define Ldim 512
#define Hdim 1024

// Scratch: [2][B][L][C] floats, channel contiguous. 256 KB (lives in L2).
__device__ float g_scratch[2 * Bdim * Ldim * Cdim];

// ---------------------------------------------------------------------------
// Kernel A (round-2/7 config, best measured): per-row dots, 2 rows per warp.
// warp w in [0, 32768): tensor = w>>14, rows idx0 = (w & 16383)*2, idx0+1.
// __ldcs streaming keeps the 268 MB out of L2's way. With the add kernel
// writing through (below), this phase carries NO output writeback debt:
// pure 268 MB read stream.
// ---------------------------------------------------------------------------
__global__ void __launch_bounds__(256) dot_kernel(
    const float* __restrict__ start,
    const float* __restrict__ end,
    const float* __restrict__ v)
{
    const unsigned warp = (blockIdx.x * blockDim.x + threadIdx.x) >> 5;
    const unsigned lane = threadIdx.x & 31;

    const unsigned tensor = warp >> 14;              // 0 or 1
    const unsigned idx0   = (warp & 16383) * 2;      // first row within tensor

    const float* base = tensor ? end : start;
    const float4* row0 = (const float4*)(base + (size_t)idx0 * Hdim);
    const float4* row1 = (const float4*)(base + (size_t)(idx0 + 1) * Hdim);
    const float4* v4   = (const float4*)(v + tensor * Hdim);

    float sum0 = 0.f, sum1 = 0.f;
#pragma unroll
    for (int k = 0; k < Hdim / 4 / 32; k++) {        // 8 iterations
        float4 a0 = __ldcs(&row0[lane + 32 * k]);
        float4 a1 = __ldcs(&row1[lane + 32 * k]);
        float4 w  = v4[lane + 32 * k];
        sum0 += a0.x * w.x + a0.y * w.y + a0.z * w.z + a0.w * w.w;
        sum1 += a1.x * w.x + a1.y * w.y + a1.z * w.z + a1.w * w.w;
    }
#pragma unroll
    for (int o = 16; o; o >>= 1) {
        sum0 += __shfl_xor_sync(0xFFFFFFFFu, sum0, o);
        sum1 += __shfl_xor_sync(0xFFFFFFFFu, sum1, o);
    }

    if (lane == 0) {
        const unsigned b = idx0 >> 13;
        const unsigned c = (idx0 >> 9) & (Cdim - 1);
        const unsigned l = idx0 & (Ldim - 1);
        float* dst = &g_scratch[((tensor * Bdim + b) * Ldim + l) * Cdim + c];
        dst[0]    = sum0;
        dst[Cdim] = sum1;
    }
}

// ---------------------------------------------------------------------------
// Kernel B (round-2 structure, best measured) with WRITE-THROUGH stores:
// __stwt sends the output to DRAM during THIS kernel (DRAM otherwise idle
// here) and leaves L2 lines clean, so the next replay's dot phase carries
// no writeback debt. Block covers (b, 8 i's, 64 j's, 16 c) = 32 KB output.
// ---------------------------------------------------------------------------
__global__ void __launch_bounds__(256) add_kernel(float4* __restrict__ out)
{
    __shared__ float4 e_sm[64 * 4];   // [j][q]
    __shared__ float4 s_sm[8 * 4];    // [i][q]

    const unsigned bx = blockIdx.x;
    const unsigned jt = bx & 7;           // j tile (64 j each)
    const unsigned it = (bx >> 3) & 63;   // i tile (8 i each)
    const unsigned b  = bx >> 9;

    const unsigned t = threadIdx.x;
    const float4* sc4 = (const float4*)g_scratch;   // [2][B][L][4] float4

    e_sm[t] = sc4[((Bdim + b) * Ldim + jt * 64) * (Cdim / 4) + t];
    if (t < 32)
        s_sm[t] = sc4[(b * Ldim + it * 8) * (Cdim / 4) + t];
    __syncthreads();

    const unsigned q = t & 3;
    const unsigned j = t >> 2;
    const float4 e = e_sm[j * 4 + q];

    float4* dst = &out[(((b * Ldim + it * 8) * Ldim) + jt * 64 + j) * 4 + q];

#pragma unroll
    for (int i = 0; i < 8; i++) {
        float4 s = s_sm[i * 4 + q];
        __stwt(dst + (size_t)i * Ldim * 4,
               make_float4(s.x + e.x, s.y + e.y, s.z + e.z, s.w + e.w));
    }
}

extern "C" void kernel_launch(void* const* d_in, const int* in_sizes, int n_in,
                              void* d_out, int out_size)
{
    const float* start = (const float*)d_in[0];
    const float* end   = (const float*)d_in[1];
    const float* v     = (const float*)d_in[2];
    float4* out = (float4*)d_out;

    // Kernel A: 32768 warps (2 rows each) = 4096 blocks x 256 threads
    dot_kernel<<<4096, 256>>>(start, end, v);

    // Kernel B: 4 b x 64 i-tiles x 8 j-tiles = 2048 blocks x 256 threads
    add_kernel<<<2048, 256>>>(out);
}

// round 15
// speedup vs baseline: 1.2513x; 1.0046x over previous
#include <cuda_runtime.h>

// Problem constants
#define Bdim 4
#define Cdim 16
#define Ldim 512
#define Hdim 1024

// Scratch: [2][B][L][C] floats, channel contiguous. 256 KB (lives in L2).
__device__ float g_scratch[2 * Bdim * Ldim * Cdim];

// ---------------------------------------------------------------------------
// Kernel A (round-2/7 config, best measured — unchanged): per-row dots,
// 2 rows per warp. warp w in [0, 32768): tensor = w>>14, rows idx0, idx0+1.
// __ldcs streaming keeps the 268 MB out of L2's way.
// ---------------------------------------------------------------------------
__global__ void __launch_bounds__(256) dot_kernel(
    const float* __restrict__ start,
    const float* __restrict__ end,
    const float* __restrict__ v)
{
    const unsigned warp = (blockIdx.x * blockDim.x + threadIdx.x) >> 5;
    const unsigned lane = threadIdx.x & 31;

    const unsigned tensor = warp >> 14;              // 0 or 1
    const unsigned idx0   = (warp & 16383) * 2;      // first row within tensor

    const float* base = tensor ? end : start;
    const float4* row0 = (const float4*)(base + (size_t)idx0 * Hdim);
    const float4* row1 = (const float4*)(base + (size_t)(idx0 + 1) * Hdim);
    const float4* v4   = (const float4*)(v + tensor * Hdim);

    float sum0 = 0.f, sum1 = 0.f;
#pragma unroll
    for (int k = 0; k < Hdim / 4 / 32; k++) {        // 8 iterations
        float4 a0 = __ldcs(&row0[lane + 32 * k]);
        float4 a1 = __ldcs(&row1[lane + 32 * k]);
        float4 w  = v4[lane + 32 * k];
        sum0 += a0.x * w.x + a0.y * w.y + a0.z * w.z + a0.w * w.w;
        sum1 += a1.x * w.x + a1.y * w.y + a1.z * w.z + a1.w * w.w;
    }
#pragma unroll
    for (int o = 16; o; o >>= 1) {
        sum0 += __shfl_xor_sync(0xFFFFFFFFu, sum0, o);
        sum1 += __shfl_xor_sync(0xFFFFFFFFu, sum1, o);
    }

    if (lane == 0) {
        const unsigned b = idx0 >> 13;
        const unsigned c = (idx0 >> 9) & (Cdim - 1);
        const unsigned l = idx0 & (Ldim - 1);
        float* dst = &g_scratch[((tensor * Bdim + b) * Ldim + l) * Cdim + c];
        dst[0]    = sum0;
        dst[Cdim] = sum1;
    }
}

// ---------------------------------------------------------------------------
// Kernel B v6: two i-tiles per block sharing one e-tile (halves scratch
// LTS re-reads), e held per-thread in a register via direct load (4
// threads/address -> L1 broadcast; no e smem, no extra barrier).
// Block covers (b, 16 i's, 64 j's, all 16 c) = 64 KB output; 1024 blocks.
// Warp stores remain 512 B fully contiguous.
// ---------------------------------------------------------------------------
__global__ void __launch_bounds__(256) add_kernel(float4* __restrict__ out)
{
    __shared__ float4 s_sm[16 * 4];   // [i][q]

    const unsigned bx = blockIdx.x;
    const unsigned jt = bx & 7;           // j tile (64 j each)
    const unsigned it = (bx >> 3) & 31;   // 16-i tile
    const unsigned b  = bx >> 8;

    const unsigned t = threadIdx.x;
    const float4* sc4 = (const float4*)g_scratch;   // [2][B][L][4] float4

    const unsigned q = t & 3;
    const unsigned j = t >> 2;                      // 0..63

    // e for this thread: direct load, L1-broadcast across the 4 q-threads.
    const float4 e = sc4[((Bdim + b) * Ldim + jt * 64 + j) * 4 + q];

    // s tile: 64 float4 cooperative load into smem.
    if (t < 64)
        s_sm[t] = sc4[(b * Ldim + it * 16) * (Cdim / 4) + t];
    __syncthreads();

    float4* dst = &out[(((b * Ldim + it * 16) * Ldim) + jt * 64 + j) * 4 + q];

#pragma unroll
    for (int i = 0; i < 16; i++) {
        float4 s = s_sm[i * 4 + q];
        dst[(size_t)i * Ldim * 4] =
            make_float4(s.x + e.x, s.y + e.y, s.z + e.z, s.w + e.w);
    }
}

extern "C" void kernel_launch(void* const* d_in, const int* in_sizes, int n_in,
                              void* d_out, int out_size)
{
    const float* start = (const float*)d_in[0];
    const float* end   = (const float*)d_in[1];
    const float* v     = (const float*)d_in[2];
    float4* out = (float4*)d_out;

    // Kernel A: 32768 warps (2 rows each) = 4096 blocks x 256 threads
    dot_kernel<<<4096, 256>>>(start, end, v);

    // Kernel B: 4 b x 32 i-tiles x 8 j-tiles = 1024 blocks x 256 threads
    add_kernel<<<1024, 256>>>(out);
}